// round 1
// baseline (speedup 1.0000x reference)
#include <cuda_runtime.h>

// ---------------- problem constants ----------------
#define BB    4
#define DIM   64
#define RANK  32
#define EE    4
#define HH    256
#define WW    256
#define HWSZ  65536          // H*W = 2^16
#define NPIX  262144         // B*H*W

// ---------------- device scratch (no cudaMalloc allowed) ----------------
__device__ float g_gate[NPIX];
__device__ int   g_idx[NPIX];
__device__ float g_W[96 * 64];                    // fused [Wq(32x64); Wkv(64x64)]
__device__ float g_qpre [(size_t)NPIX * 32];
__device__ float g_kvpre[(size_t)NPIX * 64];
__device__ float g_q    [(size_t)NPIX * 32];
__device__ float g_k    [(size_t)NPIX * 32];
__device__ float g_v    [(size_t)NPIX * 32];
__device__ float g_attn [(size_t)NPIX * 32];
__device__ float g_comb [(size_t)NPIX * 64];

// ---------------- router: softmax + top1, zero combined ----------------
__global__ void k_router(const float* __restrict__ x,
                         const float* __restrict__ rw,
                         const float* __restrict__ rb) {
    int p = blockIdx.x * blockDim.x + threadIdx.x;
    if (p >= NPIX) return;
    int b = p >> 16, s = p & 0xFFFF;
    const float* xb = x + ((size_t)b * DIM) * HWSZ + s;
    float l0 = rb[0], l1 = rb[1], l2 = rb[2], l3 = rb[3];
    #pragma unroll 4
    for (int c = 0; c < 64; c++) {
        float xv = xb[(size_t)c * HWSZ];
        l0 += rw[c] * xv;
        l1 += rw[64 + c] * xv;
        l2 += rw[128 + c] * xv;
        l3 += rw[192 + c] * xv;
    }
    float lm = l0; int am = 0;
    if (l1 > lm) { lm = l1; am = 1; }
    if (l2 > lm) { lm = l2; am = 2; }
    if (l3 > lm) { lm = l3; am = 3; }
    float sum = expf(l0 - lm) + expf(l1 - lm) + expf(l2 - lm) + expf(l3 - lm);
    g_gate[p] = 1.0f / sum;   // softmax value at the argmax
    g_idx[p]  = am;
    // zero combined
    float* cb = g_comb + ((size_t)b * DIM) * HWSZ + s;
    #pragma unroll 4
    for (int c = 0; c < 64; c++) cb[(size_t)c * HWSZ] = 0.f;
}

// ---------------- fold q_w@p0_w and kv_w@p0_w ----------------
__global__ void k_prep(const float* __restrict__ qw,   // (32,32)
                       const float* __restrict__ kvw,  // (64,32)
                       const float* __restrict__ p0) { // (32,64)
    int i = blockIdx.x * blockDim.x + threadIdx.x;
    if (i >= 96 * 64) return;
    int o = i >> 6, c = i & 63;
    float acc = 0.f;
    if (o < 32) {
        #pragma unroll
        for (int r = 0; r < 32; r++) acc += qw[o * 32 + r] * p0[r * 64 + c];
    } else {
        int oo = o - 32;
        #pragma unroll
        for (int r = 0; r < 32; r++) acc += kvw[oo * 32 + r] * p0[r * 64 + c];
    }
    g_W[i] = acc;
}

// ---------------- A: fused masked 1x1 convs -> qpre(32), kvpre(64) ----------------
__global__ __launch_bounds__(128) void k_A(const float* __restrict__ x, int e) {
    __shared__ float sW[96 * 64];
    int tid = threadIdx.x;
    for (int i = tid; i < 96 * 64; i += 128) sW[i] = g_W[i];
    __syncthreads();
    int p = blockIdx.x * 128 + tid;
    int b = p >> 16, s = p & 0xFFFF;
    float* qp = g_qpre  + ((size_t)b * 32) * HWSZ + s;
    float* kp = g_kvpre + ((size_t)b * 64) * HWSZ + s;
    float m = (g_idx[p] == e) ? g_gate[p] : 0.f;
    if (m == 0.f) {
        #pragma unroll 1
        for (int o = 0; o < 32; o++) qp[(size_t)o * HWSZ] = 0.f;
        #pragma unroll 1
        for (int o = 0; o < 64; o++) kp[(size_t)o * HWSZ] = 0.f;
        return;
    }
    float xm[64];
    const float* xb = x + ((size_t)b * DIM) * HWSZ + s;
    #pragma unroll
    for (int c = 0; c < 64; c++) xm[c] = xb[(size_t)c * HWSZ] * m;
    #pragma unroll 1
    for (int o = 0; o < 32; o++) {
        float acc = 0.f;
        #pragma unroll
        for (int c = 0; c < 64; c++) acc += sW[o * 64 + c] * xm[c];
        qp[(size_t)o * HWSZ] = acc;
    }
    #pragma unroll 1
    for (int o = 0; o < 64; o++) {
        float acc = 0.f;
        #pragma unroll
        for (int c = 0; c < 64; c++) acc += sW[(32 + o) * 64 + c] * xm[c];
        kp[(size_t)o * HWSZ] = acc;
    }
}

// ---------------- depthwise conv, 16x16 tile + halo ----------------
template <int KS, int CH, bool SPLIT>
__global__ void k_dw(const float* __restrict__ in,
                     const float* __restrict__ wgt,
                     const float* __restrict__ bias,
                     float* __restrict__ outA,
                     float* __restrict__ outB) {
    constexpr int T = 16 + KS - 1;
    __shared__ float tile[T * T];
    __shared__ float sw[KS * KS];
    int c = blockIdx.z % CH, b = blockIdx.z / CH;
    const float* ip = in + (size_t)blockIdx.z * HWSZ;
    int tid = threadIdx.y * 16 + threadIdx.x;
    if (tid < KS * KS) sw[tid] = wgt[c * KS * KS + tid];
    int by0 = blockIdx.y * 16 - KS / 2;
    int bx0 = blockIdx.x * 16 - KS / 2;
    for (int i = tid; i < T * T; i += 256) {
        int ly = i / T, lx = i - ly * T;
        int gy = by0 + ly, gx = bx0 + lx;
        tile[i] = (gy >= 0 && gy < HH && gx >= 0 && gx < WW) ? ip[gy * WW + gx] : 0.f;
    }
    __syncthreads();
    float acc = bias[c];
    #pragma unroll
    for (int ky = 0; ky < KS; ky++)
        #pragma unroll
        for (int kx = 0; kx < KS; kx++)
            acc += sw[ky * KS + kx] * tile[(threadIdx.y + ky) * T + threadIdx.x + kx];
    int oy = blockIdx.y * 16 + threadIdx.y;
    int ox = blockIdx.x * 16 + threadIdx.x;
    float* op;
    if (SPLIT) {
        op = (c < CH / 2)
           ? outA + ((size_t)(b * (CH / 2) + c)) * HWSZ
           : outB + ((size_t)(b * (CH / 2) + c - CH / 2)) * HWSZ;
    } else {
        op = outA + (size_t)blockIdx.z * HWSZ;
    }
    op[oy * WW + ox] = acc;
}

// ---------------- patch attention: 8x8 circular conv(q,k) ----------------
__global__ __launch_bounds__(256) void k_attn() {
    __shared__ float sq[32][64];
    __shared__ float sk[32][64];
    int tid = threadIdx.x;
    int grp = tid >> 3, i = tid & 7;
    int g = blockIdx.x * 32 + grp;            // patch-channel id, 0..131071
    int plane = g >> 10;                      // b*32 + c
    int sp = g & 1023;
    int ph = sp >> 5, pw = sp & 31;
    size_t base = (size_t)plane * HWSZ + (ph * 8) * WW + pw * 8;
    const float* qp = g_q + base;
    const float* kp = g_k + base;
    #pragma unroll
    for (int j = 0; j < 8; j++) {
        sq[grp][i * 8 + j] = qp[i * WW + j];
        sk[grp][i * 8 + j] = kp[i * WW + j];
    }
    __syncthreads();
    const float* q = sq[grp];
    const float* k = sk[grp];
    float out[8] = {0, 0, 0, 0, 0, 0, 0, 0};
    #pragma unroll
    for (int a = 0; a < 8; a++) {
        int ia = (i - a) & 7;
        float kr[8];
        #pragma unroll
        for (int t = 0; t < 8; t++) kr[t] = k[ia * 8 + t];
        #pragma unroll
        for (int bb = 0; bb < 8; bb++) {
            float qv = q[a * 8 + bb];
            #pragma unroll
            for (int j = 0; j < 8; j++) out[j] += qv * kr[(j - bb) & 7];
        }
    }
    float* op = g_attn + (size_t)plane * HWSZ + (ph * 8 + i) * WW + pw * 8;
    #pragma unroll
    for (int j = 0; j < 8; j++) op[j] = out[j];
}

// ---------------- fused epilogue: LN, *v, fp, gate, p2, combine ----------------
__global__ __launch_bounds__(128) void k_D(const float* __restrict__ x,
                                           const float* __restrict__ sh,
                                           const float* __restrict__ fpw,
                                           const float* __restrict__ fpb,
                                           const float* __restrict__ p1w,
                                           const float* __restrict__ p2w,
                                           const float* __restrict__ lnw,
                                           const float* __restrict__ lnb,
                                           int e) {
    __shared__ float s_fp[32 * 32];
    __shared__ float s_p1[32 * 64];
    __shared__ float s_p2[64 * 32];
    __shared__ float s_fpb[32], s_lnw[32], s_lnb[32];
    int tid = threadIdx.x;
    for (int i = tid; i < 1024; i += 128) s_fp[i] = fpw[i];
    for (int i = tid; i < 2048; i += 128) s_p1[i] = p1w[i];
    for (int i = tid; i < 2048; i += 128) s_p2[i] = p2w[i];
    if (tid < 32) { s_fpb[tid] = fpb[tid]; s_lnw[tid] = lnw[tid]; s_lnb[tid] = lnb[tid]; }
    __syncthreads();

    int p = blockIdx.x * 128 + tid;
    int b = p >> 16, s = p & 0xFFFF;
    float m = (g_idx[p] == e) ? g_gate[p] : 0.f;
    if (m == 0.f) return;

    // gate path: gacc[o] = p1 @ shared
    float gacc[32];
    #pragma unroll
    for (int o = 0; o < 32; o++) gacc[o] = 0.f;
    const float* shb = sh + ((size_t)b * DIM) * HWSZ + s;
    #pragma unroll 1
    for (int c = 0; c < 64; c++) {
        float shv = shb[(size_t)c * HWSZ];
        #pragma unroll
        for (int o = 0; o < 32; o++) gacc[o] += s_p1[o * 64 + c] * shv;
    }

    // LN over channels of attn, multiply v
    const float* ap = g_attn + ((size_t)b * 32) * HWSZ + s;
    const float* vp = g_v    + ((size_t)b * 32) * HWSZ + s;
    float t[32];
    float sum = 0.f, sq = 0.f;
    #pragma unroll
    for (int r = 0; r < 32; r++) {
        t[r] = ap[(size_t)r * HWSZ];
        sum += t[r];
        sq  += t[r] * t[r];
    }
    float mean = sum * (1.f / 32.f);
    float var  = sq * (1.f / 32.f) - mean * mean;
    float inv  = rsqrtf(var + 1e-5f);
    #pragma unroll
    for (int r = 0; r < 32; r++)
        t[r] = ((t[r] - mean) * inv * s_lnw[r] + s_lnb[r]) * vp[(size_t)r * HWSZ];

    // body*gate
    float bg[32];
    #pragma unroll
    for (int o = 0; o < 32; o++) {
        float acc = s_fpb[o];
        #pragma unroll
        for (int r = 0; r < 32; r++) acc += s_fp[o * 32 + r] * t[r];
        float z = m * gacc[o];
        float sg = z / (1.f + expf(-z));
        bg[o] = acc * sg;
    }

    // p2 projection + residual, scaled by m
    const float* xb = x + ((size_t)b * DIM) * HWSZ + s;
    float* cb = g_comb + ((size_t)b * DIM) * HWSZ + s;
    float m2 = m * m;
    #pragma unroll 1
    for (int oc = 0; oc < 64; oc++) {
        float acc = 0.f;
        #pragma unroll
        for (int r = 0; r < 32; r++) acc += s_p2[oc * 32 + r] * bg[r];
        cb[(size_t)oc * HWSZ] = m * acc + m2 * xb[(size_t)oc * HWSZ];
    }
}

// ---------------- final 64x64 output conv ----------------
__global__ __launch_bounds__(128) void k_out(const float* __restrict__ ow,
                                             const float* __restrict__ ob,
                                             float* __restrict__ out) {
    __shared__ float sW[64 * 64];
    __shared__ float sB[64];
    int tid = threadIdx.x;
    for (int i = tid; i < 4096; i += 128) sW[i] = ow[i];
    if (tid < 64) sB[tid] = ob[tid];
    __syncthreads();
    int p = blockIdx.x * 128 + tid;
    int b = p >> 16, s = p & 0xFFFF;
    const float* cb = g_comb + ((size_t)b * DIM) * HWSZ + s;
    float cv[64];
    #pragma unroll
    for (int c = 0; c < 64; c++) cv[c] = cb[(size_t)c * HWSZ];
    float* ob_ = out + ((size_t)b * DIM) * HWSZ + s;
    #pragma unroll 1
    for (int o = 0; o < 64; o++) {
        float acc = sB[o];
        #pragma unroll
        for (int c = 0; c < 64; c++) acc += sW[o * 64 + c] * cv[c];
        ob_[(size_t)o * HWSZ] = acc;
    }
}

// ---------------- launch ----------------
extern "C" void kernel_launch(void* const* d_in, const int* in_sizes, int n_in,
                              void* d_out, int out_size) {
    const float* x     = (const float*)d_in[0];
    const float* sh    = (const float*)d_in[1];
    const float* rw    = (const float*)d_in[2];
    const float* rb    = (const float*)d_in[3];
    const float* p0w   = (const float*)d_in[4];
    const float* p1w   = (const float*)d_in[5];
    const float* p2w   = (const float*)d_in[6];
    const float* qw    = (const float*)d_in[7];
    const float* qdww  = (const float*)d_in[8];
    const float* qdwb  = (const float*)d_in[9];
    const float* kvw   = (const float*)d_in[10];
    const float* kvdww = (const float*)d_in[11];
    const float* kvdwb = (const float*)d_in[12];
    const float* lnw   = (const float*)d_in[13];
    const float* lnb   = (const float*)d_in[14];
    const float* fpw   = (const float*)d_in[15];
    const float* fpb   = (const float*)d_in[16];
    const float* outw  = (const float*)d_in[17];
    const float* outb  = (const float*)d_in[18];
    float* out = (float*)d_out;

    k_router<<<NPIX / 128, 128>>>(x, rw, rb);

    for (int e = 0; e < EE; e++) {
        k_prep<<<(96 * 64 + 255) / 256, 256>>>(qw + e * 32 * 32,
                                               kvw + e * 64 * 32,
                                               p0w + e * 32 * 64);
        k_A<<<NPIX / 128, 128>>>(x, e);

        dim3 blk(16, 16);
        dim3 g3(WW / 16, HH / 16, BB * 32);
        k_dw<3, 32, false><<<g3, blk>>>(g_qpre, qdww + e * 32 * 9, qdwb + e * 32,
                                        g_q, nullptr);
        dim3 g7(WW / 16, HH / 16, BB * 64);
        k_dw<7, 64, true><<<g7, blk>>>(g_kvpre, kvdww + e * 64 * 49, kvdwb + e * 64,
                                       g_k, g_v);

        k_attn<<<(BB * 32 * 32 * 32) / 32, 256>>>();

        k_D<<<NPIX / 128, 128>>>(x, sh,
                                 fpw + e * 32 * 32, fpb + e * 32,
                                 p1w + e * 32 * 64, p2w + e * 64 * 32,
                                 lnw + e * 32, lnb + e * 32, e);
    }

    k_out<<<NPIX / 128, 128>>>(outw, outb, out);
}

// round 2
// speedup vs baseline: 1.0008x; 1.0008x over previous
#include <cuda_runtime.h>

// ---------------- problem constants ----------------
#define BB    4
#define DIM   64
#define RANK  32
#define EE    4
#define HH    256
#define WW    256
#define HWSZ  65536          // H*W = 2^16
#define NPIX  262144         // B*H*W

// ---------------- device scratch (no cudaMalloc allowed) ----------------
__device__ float g_gate[NPIX];
__device__ int   g_idx[NPIX];
__device__ float g_W[96 * 64];                    // fused [Wq(32x64); Wkv(64x64)]
__device__ float g_qpre [(size_t)NPIX * 32];
__device__ float g_kvpre[(size_t)NPIX * 64];
__device__ float g_q    [(size_t)NPIX * 32];
__device__ float g_k    [(size_t)NPIX * 32];
__device__ float g_v    [(size_t)NPIX * 32];
__device__ float g_attn [(size_t)NPIX * 32];
__device__ float g_comb [(size_t)NPIX * 64];

// ---------------- router: softmax + top1, zero combined ----------------
__global__ void k_router(const float* __restrict__ x,
                         const float* __restrict__ rw,
                         const float* __restrict__ rb) {
    int p = blockIdx.x * blockDim.x + threadIdx.x;
    if (p >= NPIX) return;
    int b = p >> 16, s = p & 0xFFFF;
    const float* xb = x + ((size_t)b * DIM) * HWSZ + s;
    float l0 = rb[0], l1 = rb[1], l2 = rb[2], l3 = rb[3];
    #pragma unroll 4
    for (int c = 0; c < 64; c++) {
        float xv = xb[(size_t)c * HWSZ];
        l0 += rw[c] * xv;
        l1 += rw[64 + c] * xv;
        l2 += rw[128 + c] * xv;
        l3 += rw[192 + c] * xv;
    }
    float lm = l0; int am = 0;
    if (l1 > lm) { lm = l1; am = 1; }
    if (l2 > lm) { lm = l2; am = 2; }
    if (l3 > lm) { lm = l3; am = 3; }
    float sum = expf(l0 - lm) + expf(l1 - lm) + expf(l2 - lm) + expf(l3 - lm);
    g_gate[p] = 1.0f / sum;   // softmax value at the argmax
    g_idx[p]  = am;
    // zero combined
    float* cb = g_comb + ((size_t)b * DIM) * HWSZ + s;
    #pragma unroll 4
    for (int c = 0; c < 64; c++) cb[(size_t)c * HWSZ] = 0.f;
}

// ---------------- fold q_w@p0_w and kv_w@p0_w ----------------
__global__ void k_prep(const float* __restrict__ qw,   // (32,32)
                       const float* __restrict__ kvw,  // (64,32)
                       const float* __restrict__ p0) { // (32,64)
    int i = blockIdx.x * blockDim.x + threadIdx.x;
    if (i >= 96 * 64) return;
    int o = i >> 6, c = i & 63;
    float acc = 0.f;
    if (o < 32) {
        #pragma unroll
        for (int r = 0; r < 32; r++) acc += qw[o * 32 + r] * p0[r * 64 + c];
    } else {
        int oo = o - 32;
        #pragma unroll
        for (int r = 0; r < 32; r++) acc += kvw[oo * 32 + r] * p0[r * 64 + c];
    }
    g_W[i] = acc;
}

// ---------------- A: fused masked 1x1 convs -> qpre(32), kvpre(64) ----------------
__global__ __launch_bounds__(128) void k_A(const float* __restrict__ x, int e) {
    __shared__ float sW[96 * 64];
    int tid = threadIdx.x;
    for (int i = tid; i < 96 * 64; i += 128) sW[i] = g_W[i];
    __syncthreads();
    int p = blockIdx.x * 128 + tid;
    int b = p >> 16, s = p & 0xFFFF;
    float* qp = g_qpre  + ((size_t)b * 32) * HWSZ + s;
    float* kp = g_kvpre + ((size_t)b * 64) * HWSZ + s;
    float m = (g_idx[p] == e) ? g_gate[p] : 0.f;
    if (m == 0.f) {
        #pragma unroll 1
        for (int o = 0; o < 32; o++) qp[(size_t)o * HWSZ] = 0.f;
        #pragma unroll 1
        for (int o = 0; o < 64; o++) kp[(size_t)o * HWSZ] = 0.f;
        return;
    }
    float xm[64];
    const float* xb = x + ((size_t)b * DIM) * HWSZ + s;
    #pragma unroll
    for (int c = 0; c < 64; c++) xm[c] = xb[(size_t)c * HWSZ] * m;
    #pragma unroll 1
    for (int o = 0; o < 32; o++) {
        float acc = 0.f;
        #pragma unroll
        for (int c = 0; c < 64; c++) acc += sW[o * 64 + c] * xm[c];
        qp[(size_t)o * HWSZ] = acc;
    }
    #pragma unroll 1
    for (int o = 0; o < 64; o++) {
        float acc = 0.f;
        #pragma unroll
        for (int c = 0; c < 64; c++) acc += sW[(32 + o) * 64 + c] * xm[c];
        kp[(size_t)o * HWSZ] = acc;
    }
}

// ---------------- depthwise conv, 16x16 tile + halo ----------------
template <int KS, int CH, bool SPLIT>
__global__ void k_dw(const float* __restrict__ in,
                     const float* __restrict__ wgt,
                     const float* __restrict__ bias,
                     float* __restrict__ outA,
                     float* __restrict__ outB) {
    constexpr int T = 16 + KS - 1;
    __shared__ float tile[T * T];
    __shared__ float sw[KS * KS];
    int c = blockIdx.z % CH, b = blockIdx.z / CH;
    const float* ip = in + (size_t)blockIdx.z * HWSZ;
    int tid = threadIdx.y * 16 + threadIdx.x;
    if (tid < KS * KS) sw[tid] = wgt[c * KS * KS + tid];
    int by0 = blockIdx.y * 16 - KS / 2;
    int bx0 = blockIdx.x * 16 - KS / 2;
    for (int i = tid; i < T * T; i += 256) {
        int ly = i / T, lx = i - ly * T;
        int gy = by0 + ly, gx = bx0 + lx;
        tile[i] = (gy >= 0 && gy < HH && gx >= 0 && gx < WW) ? ip[gy * WW + gx] : 0.f;
    }
    __syncthreads();
    float acc = bias[c];
    #pragma unroll
    for (int ky = 0; ky < KS; ky++)
        #pragma unroll
        for (int kx = 0; kx < KS; kx++)
            acc += sw[ky * KS + kx] * tile[(threadIdx.y + ky) * T + threadIdx.x + kx];
    int oy = blockIdx.y * 16 + threadIdx.y;
    int ox = blockIdx.x * 16 + threadIdx.x;
    float* op;
    if (SPLIT) {
        op = (c < CH / 2)
           ? outA + ((size_t)(b * (CH / 2) + c)) * HWSZ
           : outB + ((size_t)(b * (CH / 2) + c - CH / 2)) * HWSZ;
    } else {
        op = outA + (size_t)blockIdx.z * HWSZ;
    }
    op[oy * WW + ox] = acc;
}

// ---------------- patch attention: 8x8 circular conv(q,k) ----------------
__global__ __launch_bounds__(256) void k_attn() {
    __shared__ float sq[32][64];
    __shared__ float sk[32][64];
    int tid = threadIdx.x;
    int grp = tid >> 3, i = tid & 7;
    int g = blockIdx.x * 32 + grp;            // patch-channel id, 0..131071
    int plane = g >> 10;                      // b*32 + c
    int sp = g & 1023;
    int ph = sp >> 5, pw = sp & 31;
    size_t base = (size_t)plane * HWSZ + (ph * 8) * WW + pw * 8;
    const float* qp = g_q + base;
    const float* kp = g_k + base;
    #pragma unroll
    for (int j = 0; j < 8; j++) {
        sq[grp][i * 8 + j] = qp[i * WW + j];
        sk[grp][i * 8 + j] = kp[i * WW + j];
    }
    __syncthreads();
    const float* q = sq[grp];
    const float* k = sk[grp];
    float out[8] = {0, 0, 0, 0, 0, 0, 0, 0};
    #pragma unroll
    for (int a = 0; a < 8; a++) {
        int ia = (i - a) & 7;
        float kr[8];
        #pragma unroll
        for (int t = 0; t < 8; t++) kr[t] = k[ia * 8 + t];
        #pragma unroll
        for (int bb = 0; bb < 8; bb++) {
            float qv = q[a * 8 + bb];
            #pragma unroll
            for (int j = 0; j < 8; j++) out[j] += qv * kr[(j - bb) & 7];
        }
    }
    float* op = g_attn + (size_t)plane * HWSZ + (ph * 8 + i) * WW + pw * 8;
    #pragma unroll
    for (int j = 0; j < 8; j++) op[j] = out[j];
}

// ---------------- fused epilogue: LN, *v, fp, gate, p2, combine ----------------
__global__ __launch_bounds__(128) void k_D(const float* __restrict__ x,
                                           const float* __restrict__ sh,
                                           const float* __restrict__ fpw,
                                           const float* __restrict__ fpb,
                                           const float* __restrict__ p1w,
                                           const float* __restrict__ p2w,
                                           const float* __restrict__ lnw,
                                           const float* __restrict__ lnb,
                                           int e) {
    __shared__ float s_fp[32 * 32];
    __shared__ float s_p1[32 * 64];
    __shared__ float s_p2[64 * 32];
    __shared__ float s_fpb[32], s_lnw[32], s_lnb[32];
    int tid = threadIdx.x;
    for (int i = tid; i < 1024; i += 128) s_fp[i] = fpw[i];
    for (int i = tid; i < 2048; i += 128) s_p1[i] = p1w[i];
    for (int i = tid; i < 2048; i += 128) s_p2[i] = p2w[i];
    if (tid < 32) { s_fpb[tid] = fpb[tid]; s_lnw[tid] = lnw[tid]; s_lnb[tid] = lnb[tid]; }
    __syncthreads();

    int p = blockIdx.x * 128 + tid;
    int b = p >> 16, s = p & 0xFFFF;
    float m = (g_idx[p] == e) ? g_gate[p] : 0.f;
    if (m == 0.f) return;

    // gate path: gacc[o] = p1 @ shared
    float gacc[32];
    #pragma unroll
    for (int o = 0; o < 32; o++) gacc[o] = 0.f;
    const float* shb = sh + ((size_t)b * DIM) * HWSZ + s;
    #pragma unroll 1
    for (int c = 0; c < 64; c++) {
        float shv = shb[(size_t)c * HWSZ];
        #pragma unroll
        for (int o = 0; o < 32; o++) gacc[o] += s_p1[o * 64 + c] * shv;
    }

    // LN over channels of attn, multiply v
    const float* ap = g_attn + ((size_t)b * 32) * HWSZ + s;
    const float* vp = g_v    + ((size_t)b * 32) * HWSZ + s;
    float t[32];
    float sum = 0.f, sq = 0.f;
    #pragma unroll
    for (int r = 0; r < 32; r++) {
        t[r] = ap[(size_t)r * HWSZ];
        sum += t[r];
        sq  += t[r] * t[r];
    }
    float mean = sum * (1.f / 32.f);
    float var  = sq * (1.f / 32.f) - mean * mean;
    float inv  = rsqrtf(var + 1e-5f);
    #pragma unroll
    for (int r = 0; r < 32; r++)
        t[r] = ((t[r] - mean) * inv * s_lnw[r] + s_lnb[r]) * vp[(size_t)r * HWSZ];

    // body*gate
    float bg[32];
    #pragma unroll
    for (int o = 0; o < 32; o++) {
        float acc = s_fpb[o];
        #pragma unroll
        for (int r = 0; r < 32; r++) acc += s_fp[o * 32 + r] * t[r];
        float z = m * gacc[o];
        float sg = z / (1.f + expf(-z));
        bg[o] = acc * sg;
    }

    // p2 projection + residual, scaled by m
    const float* xb = x + ((size_t)b * DIM) * HWSZ + s;
    float* cb = g_comb + ((size_t)b * DIM) * HWSZ + s;
    float m2 = m * m;
    #pragma unroll 1
    for (int oc = 0; oc < 64; oc++) {
        float acc = 0.f;
        #pragma unroll
        for (int r = 0; r < 32; r++) acc += s_p2[oc * 32 + r] * bg[r];
        cb[(size_t)oc * HWSZ] = m * acc + m2 * xb[(size_t)oc * HWSZ];
    }
}

// ---------------- final 64x64 output conv ----------------
__global__ __launch_bounds__(128) void k_out(const float* __restrict__ ow,
                                             const float* __restrict__ ob,
                                             float* __restrict__ out) {
    __shared__ float sW[64 * 64];
    __shared__ float sB[64];
    int tid = threadIdx.x;
    for (int i = tid; i < 4096; i += 128) sW[i] = ow[i];
    if (tid < 64) sB[tid] = ob[tid];
    __syncthreads();
    int p = blockIdx.x * 128 + tid;
    int b = p >> 16, s = p & 0xFFFF;
    const float* cb = g_comb + ((size_t)b * DIM) * HWSZ + s;
    float cv[64];
    #pragma unroll
    for (int c = 0; c < 64; c++) cv[c] = cb[(size_t)c * HWSZ];
    float* ob_ = out + ((size_t)b * DIM) * HWSZ + s;
    #pragma unroll 1
    for (int o = 0; o < 64; o++) {
        float acc = sB[o];
        #pragma unroll
        for (int c = 0; c < 64; c++) acc += sW[o * 64 + c] * cv[c];
        ob_[(size_t)o * HWSZ] = acc;
    }
}

// ---------------- launch ----------------
extern "C" void kernel_launch(void* const* d_in, const int* in_sizes, int n_in,
                              void* d_out, int out_size) {
    const float* x     = (const float*)d_in[0];
    const float* sh    = (const float*)d_in[1];
    const float* rw    = (const float*)d_in[2];
    const float* rb    = (const float*)d_in[3];
    const float* p0w   = (const float*)d_in[4];
    const float* p1w   = (const float*)d_in[5];
    const float* p2w   = (const float*)d_in[6];
    const float* qw    = (const float*)d_in[7];
    const float* qdww  = (const float*)d_in[8];
    const float* qdwb  = (const float*)d_in[9];
    const float* kvw   = (const float*)d_in[10];
    const float* kvdww = (const float*)d_in[11];
    const float* kvdwb = (const float*)d_in[12];
    const float* lnw   = (const float*)d_in[13];
    const float* lnb   = (const float*)d_in[14];
    const float* fpw   = (const float*)d_in[15];
    const float* fpb   = (const float*)d_in[16];
    const float* outw  = (const float*)d_in[17];
    const float* outb  = (const float*)d_in[18];
    float* out = (float*)d_out;

    k_router<<<NPIX / 128, 128>>>(x, rw, rb);

    for (int e = 0; e < EE; e++) {
        k_prep<<<(96 * 64 + 255) / 256, 256>>>(qw + e * 32 * 32,
                                               kvw + e * 64 * 32,
                                               p0w + e * 32 * 64);
        k_A<<<NPIX / 128, 128>>>(x, e);

        dim3 blk(16, 16);
        dim3 g3(WW / 16, HH / 16, BB * 32);
        k_dw<3, 32, false><<<g3, blk>>>(g_qpre, qdww + e * 32 * 9, qdwb + e * 32,
                                        g_q, nullptr);
        dim3 g7(WW / 16, HH / 16, BB * 64);
        k_dw<7, 64, true><<<g7, blk>>>(g_kvpre, kvdww + e * 64 * 49, kvdwb + e * 64,
                                       g_k, g_v);

        k_attn<<<(BB * 32 * 32 * 32) / 32, 256>>>();

        k_D<<<NPIX / 128, 128>>>(x, sh,
                                 fpw + e * 32 * 32, fpb + e * 32,
                                 p1w + e * 32 * 64, p2w + e * 64 * 32,
                                 lnw + e * 32, lnb + e * 32, e);
    }

    k_out<<<NPIX / 128, 128>>>(outw, outb, out);
}